// round 9
// baseline (speedup 1.0000x reference)
#include <cuda_runtime.h>
#include <cuda_bf16.h>

// k-winners-take-all: x (rows=200704, C=256) fp32. Keep x >= 26th largest per row.
// Warp-per-row. Hot path: bisection on positive-float bit patterns, accelerated by
// a prior-seeded first probe and false-position on even iterations; odd iterations
// ALWAYS bisect => bracket halves every 2 iters => provably <= 64 iterations.
// Cold path (threshold < 0; ~never on this data, required for exactness): key radix.

constexpr int CHANNELS = 256;
constexpr unsigned KSEL = 26;   // max(1, round(0.1 * 256))

__device__ __forceinline__ void ceF(float &a, float &b) {   // a<-max, b<-min
    float hi = fmaxf(a, b), lo = fminf(a, b);
    a = hi; b = lo;
}

__device__ __forceinline__ unsigned f2k(float f) {          // order-preserving key
    unsigned u = __float_as_uint(f);
    unsigned m = (unsigned)((int)u >> 31);
    return u ^ (m | 0x80000000u);
}

__global__ void __launch_bounds__(256)
kwta_kernel(const float* __restrict__ x, float* __restrict__ y, int rows) {
    int gw = (blockIdx.x * blockDim.x + threadIdx.x) >> 5;
    if (gw >= rows) return;
    int lane = threadIdx.x & 31;

    const float4* xp = reinterpret_cast<const float4*>(x) + (size_t)gw * (CHANNELS / 4);
    float4 a = __ldcs(xp + lane);
    float4 b = __ldcs(xp + 32 + lane);

    float f0 = a.x, f1 = a.y, f2 = a.z, f3 = a.w;
    float f4 = b.x, f5 = b.y, f6 = b.z, f7 = b.w;

    // Batcher odd-even mergesort for 8, descending (19 CE)
    ceF(f0,f1); ceF(f2,f3); ceF(f4,f5); ceF(f6,f7);
    ceF(f0,f2); ceF(f1,f3); ceF(f4,f6); ceF(f5,f7);
    ceF(f1,f2); ceF(f5,f6);
    ceF(f0,f4); ceF(f1,f5); ceF(f2,f6); ceF(f3,f7);
    ceF(f2,f4); ceF(f3,f5);
    ceF(f1,f2); ceF(f3,f4); ceF(f5,f6);
    // f0 >= f1 >= ... >= f7

    // per-lane count of {f_j >= c}: branchless binary search on sorted regs
    auto cnt8 = [&](float c) -> unsigned {
        bool c1 = (f3 >= c);
        float t1 = c1 ? f5 : f1;
        bool c2 = (t1 >= c);
        float tA = c2 ? f2 : f0;
        float tB = c2 ? f6 : f4;
        float t2 = c1 ? tB : tA;
        bool c3 = (t2 >= c);
        bool c0 = (f7 >= c);
        return 4u*(unsigned)c1 + 2u*(unsigned)c2 + (unsigned)c3 + (unsigned)c0;
    };

    unsigned k0   = f2k(f0);                              // lane-max key
    unsigned keyL = __reduce_min_sync(0xFFFFFFFFu, k0);   // min lane-max (cnt_ge >= 32)
    unsigned keyM = __reduce_max_sync(0xFFFFFFFFu, k0);   // warp max

    float thrf;
    bool cold = false;
    unsigned lo = 0u;
    unsigned cntLo = 300u;   // sentinel "unprobed"; cannot fake isolation (cntHi <= 25)

    if (keyL >= 0x80000000u) {
        lo = keyL ^ 0x80000000u;          // positive pattern; cnt_ge(lo) >= 32 >= KSEL
    } else {
        unsigned cp = __reduce_add_sync(0xFFFFFFFFu, cnt8(0.0f));
        if (cp >= KSEL) { lo = 0u; cntLo = cp; }
        else            { cold = true; }                  // threshold negative
    }

    if (!cold) {
        // ---- HOT: T >= 0, search positive patterns in [lo, hi) ----
        unsigned hi = (keyM ^ 0x80000000u) + 1u;          // cnt_ge(hi) == 0 exactly
        unsigned cntHi = 0u;
        float eLo = 88.0f, eHi = 0.0f;                    // interpolation estimates
        if (cntLo <= 256u) eLo = (float)cntLo;
        unsigned thrkey = lo;
        bool isolated = false;

        #pragma unroll 1
        for (int it = 0; it < 64 && (hi - lo) > 1u; ++it) {
            unsigned w = hi - lo;
            unsigned mid;
            if (it & 1) {
                mid = lo + (w >> 1);                      // ALWAYS bisect (odd its)
            } else if (it == 0) {
                mid = lo + (w >> 5) * 19u;                // prior: ~0.59 of bracket
            } else {
                float frac = __fdividef(eLo - 25.5f, eLo - eHi);
                mid = lo + (unsigned)((float)w * frac);   // false position
            }
            // clamp strictly inside (lo, hi): guarantees progress on any branch
            if (mid <= lo) mid = lo + 1u;
            else if (mid >= hi) mid = hi - 1u;

            unsigned tot = __reduce_add_sync(0xFFFFFFFFu, cnt8(__uint_as_float(mid)));
            if (tot >= KSEL) { lo = mid; cntLo = tot; eLo = (float)tot; }
            else             { hi = mid; cntHi = tot; eHi = (float)tot; }
            if (cntLo - cntHi == 1u) { isolated = true; break; }
        }
        if (isolated) {
            // exactly one element in [float(lo), float(hi)) -> it is T
            float Uf = __uint_as_float(hi);
            float pf = __uint_as_float(lo);
            float t = f7;
            t = (f6 < Uf) ? f6 : t;
            t = (f5 < Uf) ? f5 : t;
            t = (f4 < Uf) ? f4 : t;
            t = (f3 < Uf) ? f3 : t;
            t = (f2 < Uf) ? f2 : t;
            t = (f1 < Uf) ? f1 : t;
            t = (f0 < Uf) ? f0 : t;
            unsigned m = (t >= pf && t < Uf) ? __float_as_uint(t) : 0u;
            thrkey = __reduce_max_sync(0xFFFFFFFFu, m);
        } else {
            thrkey = lo;                                  // bracket width 1: lo == bits(T)
        }
        thrf = __uint_as_float(thrkey);
    } else {
        // ---- COLD: T < 0. Exact key-domain MSB radix (rarely taken). ----
        unsigned s0 = f2k(f0), s1 = f2k(f1), s2 = f2k(f2), s3 = f2k(f3);
        unsigned s4 = f2k(f4), s5 = f2k(f5), s6 = f2k(f6), s7 = f2k(f7);
        auto kcnt8 = [&](unsigned c) -> unsigned {
            bool c1 = (s3 >= c);
            unsigned t1 = c1 ? s5 : s1;
            bool c2 = (t1 >= c);
            unsigned tA = c2 ? s2 : s0;
            unsigned tB = c2 ? s6 : s4;
            unsigned t2 = c1 ? tB : tA;
            bool c3 = (t2 >= c);
            bool c0 = (s7 >= c);
            return 4u*(unsigned)c1 + 2u*(unsigned)c2 + (unsigned)c3 + (unsigned)c0;
        };
        unsigned prefix = 0u, U = 0xFFFFFFFFu;
        unsigned cntP = 256u, cntU = 0u;
        unsigned thrkey = 0u;
        #pragma unroll 1
        for (int bit = 31; bit >= 0; --bit) {
            unsigned cand = prefix | (1u << bit);
            unsigned tot = __reduce_add_sync(0xFFFFFFFFu, kcnt8(cand));
            if (tot >= KSEL) { prefix = cand; cntP = tot; }
            else             { U = cand;      cntU = tot; }
            if (cntP - cntU == 1u) {
                unsigned t = s7;
                t = (s6 < U) ? s6 : t;
                t = (s5 < U) ? s5 : t;
                t = (s4 < U) ? s4 : t;
                t = (s3 < U) ? s3 : t;
                t = (s2 < U) ? s2 : t;
                t = (s1 < U) ? s1 : t;
                t = (s0 < U) ? s0 : t;
                unsigned m = (t >= prefix && t < U) ? t : 0u;
                prefix = __reduce_max_sync(0xFFFFFFFFu, m);
                break;
            }
        }
        thrkey = prefix;
        unsigned tu = (thrkey & 0x80000000u) ? (thrkey ^ 0x80000000u) : ~thrkey;
        thrf = __uint_as_float(tu);
    }

    float4 oa, ob;
    oa.x = (a.x >= thrf) ? a.x : 0.0f;
    oa.y = (a.y >= thrf) ? a.y : 0.0f;
    oa.z = (a.z >= thrf) ? a.z : 0.0f;
    oa.w = (a.w >= thrf) ? a.w : 0.0f;
    ob.x = (b.x >= thrf) ? b.x : 0.0f;
    ob.y = (b.y >= thrf) ? b.y : 0.0f;
    ob.z = (b.z >= thrf) ? b.z : 0.0f;
    ob.w = (b.w >= thrf) ? b.w : 0.0f;

    float4* yp = reinterpret_cast<float4*>(y) + (size_t)gw * (CHANNELS / 4);
    __stcs(yp + lane, oa);
    __stcs(yp + 32 + lane, ob);
}

extern "C" void kernel_launch(void* const* d_in, const int* in_sizes, int n_in,
                              void* d_out, int out_size) {
    const float* x = (const float*)d_in[0];
    float* y = (float*)d_out;
    int rows = in_sizes[0] / CHANNELS;            // 200704
    int total_threads = rows * 32;                // one warp per row
    int block = 256;
    int grid = (total_threads + block - 1) / block;
    kwta_kernel<<<grid, block>>>(x, y, rows);
}

// round 10
// speedup vs baseline: 1.4697x; 1.4697x over previous
#include <cuda_runtime.h>
#include <cuda_bf16.h>

// k-winners-take-all: x (rows=200704, C=256) fp32. Keep x >= 26th largest per row.
// Warp-per-row. Hot path: lean bisection on positive-float bit patterns with
// count-exact early exits (tot==26 -> min-of-winners, tot==25 -> max-of-losers)
// and a prior-placed first probe. Cold path (threshold < 0; ~never): key radix.

constexpr int CHANNELS = 256;
constexpr unsigned KSEL = 26;   // max(1, round(0.1 * 256))

__device__ __forceinline__ void ceF(float &a, float &b) {   // a<-max, b<-min
    float hi = fmaxf(a, b), lo = fminf(a, b);
    a = hi; b = lo;
}

__device__ __forceinline__ unsigned f2k(float f) {          // order-preserving key
    unsigned u = __float_as_uint(f);
    unsigned m = (unsigned)((int)u >> 31);
    return u ^ (m | 0x80000000u);
}

__global__ void __launch_bounds__(256)
kwta_kernel(const float* __restrict__ x, float* __restrict__ y, int rows) {
    int gw = (blockIdx.x * blockDim.x + threadIdx.x) >> 5;
    if (gw >= rows) return;
    int lane = threadIdx.x & 31;

    const float4* xp = reinterpret_cast<const float4*>(x) + (size_t)gw * (CHANNELS / 4);
    float4 a = __ldcs(xp + lane);
    float4 b = __ldcs(xp + 32 + lane);

    float f0 = a.x, f1 = a.y, f2 = a.z, f3 = a.w;
    float f4 = b.x, f5 = b.y, f6 = b.z, f7 = b.w;

    // Batcher odd-even mergesort for 8, descending (19 CE)
    ceF(f0,f1); ceF(f2,f3); ceF(f4,f5); ceF(f6,f7);
    ceF(f0,f2); ceF(f1,f3); ceF(f4,f6); ceF(f5,f7);
    ceF(f1,f2); ceF(f5,f6);
    ceF(f0,f4); ceF(f1,f5); ceF(f2,f6); ceF(f3,f7);
    ceF(f2,f4); ceF(f3,f5);
    ceF(f1,f2); ceF(f3,f4); ceF(f5,f6);
    // f0 >= f1 >= ... >= f7

    // per-lane count of {f_j >= c}: branchless binary search on sorted regs
    auto cnt8 = [&](float c) -> unsigned {
        bool c1 = (f3 >= c);
        float t1 = c1 ? f5 : f1;
        bool c2 = (t1 >= c);
        float tA = c2 ? f2 : f0;
        float tB = c2 ? f6 : f4;
        float t2 = c1 ? tB : tA;
        bool c3 = (t2 >= c);
        bool c0 = (f7 >= c);
        return 4u*(unsigned)c1 + 2u*(unsigned)c2 + (unsigned)c3 + (unsigned)c0;
    };

    unsigned k0   = f2k(f0);                              // lane-max key
    unsigned keyL = __reduce_min_sync(0xFFFFFFFFu, k0);   // min lane-max (cnt_ge >= 32)
    unsigned keyM = __reduce_max_sync(0xFFFFFFFFu, k0);   // warp max

    float thrf;
    bool cold = false;
    unsigned lo = 0u;

    if (keyL >= 0x80000000u) {
        lo = keyL ^ 0x80000000u;          // positive pattern; cnt_ge(lo) >= 32 >= KSEL
    } else {
        unsigned cp = __reduce_add_sync(0xFFFFFFFFu, cnt8(0.0f));
        if (cp < KSEL) cold = true;       // threshold negative
    }

    if (!cold) {
        // ---- HOT: T >= 0, bisection over positive patterns in [lo, hi) ----
        // Invariants: cnt_ge(lo) >= 26 (in fact >= 27 after any lo update),
        //             cnt_ge(hi) <= 25 (in fact <= 24 after any hi update).
        unsigned hi = (keyM ^ 0x80000000u) + 1u;          // cnt_ge(hi) == 0 exactly
        unsigned thrkey;

        if (hi - lo <= 1u) {
            thrkey = lo;                                  // bracket already width 1
        } else {
            // prior-placed first probe (~0.59 of bracket); pure bisection after
            unsigned mid = lo + ((hi - lo) >> 5) * 19u;
            if (mid == lo) mid = lo + 1u;

            #pragma unroll 1
            for (;;) {
                float c = __uint_as_float(mid);
                unsigned tot = __reduce_add_sync(0xFFFFFFFFu, cnt8(c));

                if (tot == KSEL) {
                    // exactly 26 elements >= c: T = min of them
                    float t = f0;
                    t = (f1 >= c) ? f1 : t;
                    t = (f2 >= c) ? f2 : t;
                    t = (f3 >= c) ? f3 : t;
                    t = (f4 >= c) ? f4 : t;
                    t = (f5 >= c) ? f5 : t;
                    t = (f6 >= c) ? f6 : t;
                    t = (f7 >= c) ? f7 : t;                // smallest elem >= c (if any)
                    unsigned m = (t >= c) ? __float_as_uint(t) : 0xFFFFFFFFu;
                    thrkey = __reduce_min_sync(0xFFFFFFFFu, m);
                    break;
                }
                if (tot == KSEL - 1u) {
                    // exactly 25 elements >= c: T = max of elements < c (T >= 0)
                    float t = f7;
                    t = (f6 < c) ? f6 : t;
                    t = (f5 < c) ? f5 : t;
                    t = (f4 < c) ? f4 : t;
                    t = (f3 < c) ? f3 : t;
                    t = (f2 < c) ? f2 : t;
                    t = (f1 < c) ? f1 : t;
                    t = (f0 < c) ? f0 : t;                 // largest elem < c (if any)
                    // canonicalize -0.0 -> +0.0 so uint max == float max on [0, c)
                    unsigned m = (t < c) ? __float_as_uint(fmaxf(t, 0.0f)) : 0u;
                    thrkey = __reduce_max_sync(0xFFFFFFFFu, m);
                    break;
                }
                if (tot > KSEL) lo = mid; else hi = mid;   // tot >= 27 / tot <= 24
                if (hi - lo <= 1u) { thrkey = lo; break; } // lo == bits(T) exactly
                mid = lo + ((hi - lo) >> 1);               // bisect: <= 33 iters total
            }
        }
        thrf = __uint_as_float(thrkey);
    } else {
        // ---- COLD: T < 0. Exact key-domain MSB radix (rarely taken). ----
        unsigned s0 = f2k(f0), s1 = f2k(f1), s2 = f2k(f2), s3 = f2k(f3);
        unsigned s4 = f2k(f4), s5 = f2k(f5), s6 = f2k(f6), s7 = f2k(f7);
        auto kcnt8 = [&](unsigned c) -> unsigned {
            bool c1 = (s3 >= c);
            unsigned t1 = c1 ? s5 : s1;
            bool c2 = (t1 >= c);
            unsigned tA = c2 ? s2 : s0;
            unsigned tB = c2 ? s6 : s4;
            unsigned t2 = c1 ? tB : tA;
            bool c3 = (t2 >= c);
            bool c0 = (s7 >= c);
            return 4u*(unsigned)c1 + 2u*(unsigned)c2 + (unsigned)c3 + (unsigned)c0;
        };
        unsigned prefix = 0u, U = 0xFFFFFFFFu;
        unsigned cntP = 256u, cntU = 0u;
        unsigned thrkey;
        #pragma unroll 1
        for (int bit = 31; ; --bit) {
            unsigned cand = prefix | (1u << bit);
            unsigned tot = __reduce_add_sync(0xFFFFFFFFu, kcnt8(cand));
            if (tot >= KSEL) { prefix = cand; cntP = tot; }
            else             { U = cand;      cntU = tot; }
            if (cntP - cntU == 1u) {
                unsigned t = s7;
                t = (s6 < U) ? s6 : t;
                t = (s5 < U) ? s5 : t;
                t = (s4 < U) ? s4 : t;
                t = (s3 < U) ? s3 : t;
                t = (s2 < U) ? s2 : t;
                t = (s1 < U) ? s1 : t;
                t = (s0 < U) ? s0 : t;
                unsigned m = (t >= prefix && t < U) ? t : 0u;
                thrkey = __reduce_max_sync(0xFFFFFFFFu, m);
                break;
            }
            if (bit == 0) { thrkey = prefix; break; }
        }
        unsigned tu = (thrkey & 0x80000000u) ? (thrkey ^ 0x80000000u) : ~thrkey;
        thrf = __uint_as_float(tu);
    }

    float4 oa, ob;
    oa.x = (a.x >= thrf) ? a.x : 0.0f;
    oa.y = (a.y >= thrf) ? a.y : 0.0f;
    oa.z = (a.z >= thrf) ? a.z : 0.0f;
    oa.w = (a.w >= thrf) ? a.w : 0.0f;
    ob.x = (b.x >= thrf) ? b.x : 0.0f;
    ob.y = (b.y >= thrf) ? b.y : 0.0f;
    ob.z = (b.z >= thrf) ? b.z : 0.0f;
    ob.w = (b.w >= thrf) ? b.w : 0.0f;

    float4* yp = reinterpret_cast<float4*>(y) + (size_t)gw * (CHANNELS / 4);
    __stcs(yp + lane, oa);
    __stcs(yp + 32 + lane, ob);
}

extern "C" void kernel_launch(void* const* d_in, const int* in_sizes, int n_in,
                              void* d_out, int out_size) {
    const float* x = (const float*)d_in[0];
    float* y = (float*)d_out;
    int rows = in_sizes[0] / CHANNELS;            // 200704
    int total_threads = rows * 32;                // one warp per row
    int block = 256;
    int grid = (total_threads + block - 1) / block;
    kwta_kernel<<<grid, block>>>(x, y, rows);
}